// round 15
// baseline (speedup 1.0000x reference)
#include <cuda_runtime.h>
#include <cuda_bf16.h>
#include <cstdint>

#define BB 512
#define CC 112
#define DD 128
#define HH 8
#define HDIM 16
#define KW 8
#define MM (BB*CC)   // 57344
#define NT 512

// smem word offsets
#define ASU_O   14784    // bf16 A [112][68]; attn-out overlay
#define B0_O    22400    // weight buf [128][68]
#define B1_O    31104    // weight buf [128][68]
#define KALL_O  39808    // K [112][68]
#define VT_O    47424    // V^T [128][60]
#define SMEM_W  55104    // 220416 bytes

// Scratch (allocation-free contract)
__device__ __nv_bfloat16 g_wb[4 * DD * DD];        // bf16 wq|wk|wv|wo

__device__ __forceinline__ unsigned packbf(float a, float b) {
    __nv_bfloat162 p = __floats2bfloat162_rn(a, b);
    return *reinterpret_cast<unsigned*>(&p);
}
__device__ __forceinline__ float ex2(float x) {
    float r;
    asm("ex2.approx.f32 %0, %1;" : "=f"(r) : "f"(x));
    return r;
}
__device__ __forceinline__ void mma16(float* c, const unsigned* a, const unsigned* b) {
    asm volatile(
        "mma.sync.aligned.m16n8k16.row.col.f32.bf16.bf16.f32 "
        "{%0,%1,%2,%3}, {%4,%5,%6,%7}, {%8,%9}, {%0,%1,%2,%3};"
        : "+f"(c[0]), "+f"(c[1]), "+f"(c[2]), "+f"(c[3])
        : "r"(a[0]), "r"(a[1]), "r"(a[2]), "r"(a[3]), "r"(b[0]), "r"(b[1]));
}
__device__ __forceinline__ void ldsm4(unsigned* r, unsigned addr) {
    asm volatile("ldmatrix.sync.aligned.m8n8.x4.shared.b16 {%0,%1,%2,%3}, [%4];"
        : "=r"(r[0]), "=r"(r[1]), "=r"(r[2]), "=r"(r[3]) : "r"(addr));
}
__device__ __forceinline__ void stsm2(unsigned addr, unsigned r0, unsigned r1) {
    asm volatile("stmatrix.sync.aligned.m8n8.x2.shared.b16 [%0], {%1,%2};"
        :: "r"(addr), "r"(r0), "r"(r1) : "memory");
}
__device__ __forceinline__ void stsm2t(unsigned addr, unsigned r0, unsigned r1) {
    asm volatile("stmatrix.sync.aligned.m8n8.x2.trans.shared.b16 [%0], {%1,%2};"
        :: "r"(addr), "r"(r0), "r"(r1) : "memory");
}
__device__ __forceinline__ void stsm4(unsigned addr, unsigned r0, unsigned r1,
                                      unsigned r2, unsigned r3) {
    asm volatile("stmatrix.sync.aligned.m8n8.x4.shared.b16 [%0], {%1,%2,%3,%4};"
        :: "r"(addr), "r"(r0), "r"(r1), "r"(r2), "r"(r3) : "memory");
}
__device__ __forceinline__ unsigned su(const void* p) {
    return (unsigned)__cvta_generic_to_shared(p);
}
__device__ __forceinline__ void cpa16(unsigned dst, const void* src) {
    asm volatile("cp.async.cg.shared.global [%0], [%1], 16;" :: "r"(dst), "l"(src));
}
#define CP_COMMIT() asm volatile("cp.async.commit_group;")
#define CP_WAIT0()  asm volatile("cp.async.wait_group 0;")

// ---------------------------------------------------------------------------
// Kernel 0: weights fp32 -> bf16 (wq|wk|wv|wo)
// ---------------------------------------------------------------------------
__global__ void k_prep(const float* __restrict__ wq, const float* __restrict__ wk,
                       const float* __restrict__ wv, const float* __restrict__ wo) {
    int m = blockIdx.x >> 4;
    const float* s = (m == 0) ? wq : (m == 1) ? wk : (m == 2) ? wv : wo;
    int i = ((blockIdx.x & 15) * 256 + threadIdx.x) * 4;
    float4 v = *(const float4*)(s + i);
    uint2 p = {packbf(v.x, v.y), packbf(v.z, v.w)};
    *(uint2*)(g_wb + m * DD * DD + i) = p;
}

// ---------------------------------------------------------------------------
// Kernel 1 (FULLY FUSED): conv -> QKV -> attention(paired single-pass)
//                          -> outproj -> LN. 512 threads, 220.4KB smem.
// ---------------------------------------------------------------------------
__global__ void __launch_bounds__(NT) k_fused(
        const float* __restrict__ x,
        const float* __restrict__ cw, const float* __restrict__ cb,
        const float* __restrict__ bg, const float* __restrict__ bbias,
        const float* __restrict__ bm, const float* __restrict__ bvv,
        const float* __restrict__ bq, const float* __restrict__ bk,
        const float* __restrict__ bvp, const float* __restrict__ bo,
        const float* __restrict__ lg, const float* __restrict__ lb,
        float* __restrict__ out) {
    extern __shared__ unsigned smu[];
    float*    Ssrc = (float*)smu;          // [112][132] fp32
    unsigned* Asu  = smu + ASU_O;
    unsigned* B0   = smu + B0_O;
    unsigned* B1   = smu + B1_O;
    unsigned* kall = smu + KALL_O;
    unsigned* vt   = smu + VT_O;

    int tid = threadIdx.x;
    int b = blockIdx.x;
    int lane = tid & 31, warp = tid >> 5;   // 16 warps
    int wm = warp >> 2, wn = warp & 3;      // 4 x 4, warp tile 32x32
    int gr = lane >> 2, gc = lane & 3;

    int arow = (lane & 7) + ((lane >> 3) & 1) * 8;
    int acolw = (lane >> 4) * 4;
    int brow = (lane & 7) + ((lane >> 4) & 1) * 8;
    int bcolw = ((lane >> 3) & 1) * 4;

    // ================= stage x (fp32) + wq (bf16) =================
    const char* xg = (const char*)(x + (size_t)b * CC * DD);
#pragma unroll
    for (int i = tid; i < 3584; i += NT) {
        int row = i >> 5, c4 = (i & 31) * 4;
        cpa16(su(Ssrc + row * 132 + c4), xg + (row * 128 + c4) * 4);
    }
#pragma unroll
    for (int i = tid; i < 2048; i += NT) {
        int row = i >> 4, q4 = i & 15;
        cpa16(su(B0 + row * 68 + q4 * 4), (const char*)g_wb + i * 16);
    }
    CP_COMMIT(); CP_WAIT0();
    __syncthreads();

    // ================= conv -> GELU -> BN -> residual (in smem) ============
    {
#pragma unroll
        for (int rr = 0; rr < 7; rr++) {
            int row = warp * 7 + rr;
            int c0 = lane * 4;
            float xin[11];
#pragma unroll
            for (int j = 0; j < 11; j++) {
                int idx = c0 - 3 + j;
                xin[j] = (idx >= 0 && idx < DD) ? Ssrc[row * 132 + idx] : 0.f;
            }
            float w[KW];
#pragma unroll
            for (int k = 0; k < KW; k++) w[k] = cw[row * KW + k];
            float cbias = cb[row];
            float bnsc = bg[row] * rsqrtf(bvv[row] + 1e-5f);
            float bnm = bm[row], bnb = bbias[row];
            __syncwarp();
            float so[4];
#pragma unroll
            for (int j = 0; j < 4; j++) {
                float acc = 0.f;
#pragma unroll
                for (int k = 0; k < KW; k++) acc += xin[j + k] * w[k];
                acc += cbias;
                float g = 0.5f * acc * (1.f + erff(acc * 0.70710678118654752f));
                float h = (g - bnm) * bnsc + bnb;
                so[j] = xin[j + 3] + h;
            }
            *(float4*)&Ssrc[row * 132 + c0] = make_float4(so[0], so[1], so[2], so[3]);
            Asu[row * 68 + (c0 >> 1)]     = packbf(so[0], so[1]);
            Asu[row * 68 + (c0 >> 1) + 1] = packbf(so[2], so[3]);
        }
    }
    __syncthreads();

    unsigned abase[2];
    abase[0] = su(Asu + (wm * 32 + arow) * 68 + acolw);
    abase[1] = su(Asu + (wm * 32 + 16 + arow) * 68 + acolw);

    unsigned qf[4][4];   // register-resident Q fragments (2 used when wm==3)

    // ================= QKV GEMMs (double-buffered weights) =================
    for (int sel = 0; sel < 3; sel++) {
        {   // prefetch next weight matrix (wk, wv, then wo)
            const char* nw = (const char*)g_wb + (size_t)((sel < 2) ? sel + 1 : 3) * 32768;
            unsigned* dstb = (sel == 1) ? B0 : B1;
#pragma unroll
            for (int i = tid; i < 2048; i += NT) {
                int row = i >> 4, q4 = i & 15;
                cpa16(su(dstb + row * 68 + q4 * 4), nw + i * 16);
            }
            CP_COMMIT();
        }
        unsigned* Bsu = (sel & 1) ? B1 : B0;
        unsigned bbase[2];
        bbase[0] = su(Bsu + (wn * 32 + brow) * 68 + bcolw);
        bbase[1] = su(Bsu + (wn * 32 + 16 + brow) * 68 + bcolw);

        float c[2][4][4] = {};
#pragma unroll
        for (int kw = 0; kw < 64; kw += 8) {
            unsigned a[2][4], bb[2][4];
            ldsm4(a[0], abase[0] + kw * 4);
            if (wm < 3) ldsm4(a[1], abase[1] + kw * 4);
            ldsm4(bb[0], bbase[0] + kw * 4);
            ldsm4(bb[1], bbase[1] + kw * 4);
#pragma unroll
            for (int ni = 0; ni < 4; ni++) {
                mma16(c[0][ni], a[0], &bb[ni >> 1][(ni & 1) * 2]);
                if (wm < 3) mma16(c[1][ni], a[1], &bb[ni >> 1][(ni & 1) * 2]);
            }
        }

        const float* bias = (sel == 0) ? bq : (sel == 1) ? bk : bvp;
#pragma unroll
        for (int mi = 0; mi < 2; mi++) {
            if (wm == 3 && mi == 1) continue;   // rows 112..127 are padding
            int R0 = wm * 32 + mi * 16;
#pragma unroll
            for (int ni = 0; ni < 4; ni++) {
                int C0 = wn * 32 + ni * 8;
                int col = C0 + 2 * gc;
                float v0 = c[mi][ni][0] + bias[col];
                float v1 = c[mi][ni][1] + bias[col + 1];
                float v2 = c[mi][ni][2] + bias[col];
                float v3 = c[mi][ni][3] + bias[col + 1];
                if (sel == 0) {
                    int hp = ni >> 1, p = ni & 1;
                    int idx = mi * 2 + hp;
                    qf[idx][p * 2]     = packbf(v0, v1);
                    qf[idx][p * 2 + 1] = packbf(v2, v3);
                } else if (sel == 1) {
                    unsigned ad = su(kall) + 4 * ((R0 + (lane & 15)) * 68 + (C0 >> 1));
                    stsm2(ad, packbf(v0, v1), packbf(v2, v3));
                } else {
                    unsigned ad = su(vt) + (C0 + (lane & 7)) * 240 + (R0 + (lane & 8)) * 2;
                    stsm2t(ad, packbf(v0, v1), packbf(v2, v3));
                }
            }
        }
        if (sel < 2) { CP_WAIT0(); __syncthreads(); }
        else         { __syncthreads(); }   // kall/vt visible; wo still in flight
    }

    // ================= Attention: paired single-pass ==============
    // Both m-tiles of a head share the SAME K/V fragments: 1 K-ldsm + 1 V-ldsm
    // feed 8 mmas + 16 ex2 per bj. Normalization deferred (bit-identical).
    const float Cst = 0.25f * 1.44269504088896f;
#pragma unroll
    for (int hp = 0; hp < 2; hp++) {
        int h = wn * 2 + hp;
        const unsigned* aq0 = qf[hp];
        const unsigned* aq1 = qf[2 + hp];
        bool two = (wm < 3);

        float sA0 = 0.f, sA1 = 0.f, sB0 = 0.f, sB1 = 0.f;
        float oA[2][4] = {}, oB[2][4] = {};
        unsigned kb = su(kall + (brow) * 68 + h * 8 + bcolw);
        unsigned bpv = su(vt + (h * 16 + brow) * 60 + bcolw);
#pragma unroll
        for (int bj = 0; bj < 7; bj++) {
            unsigned bbk[4];
            ldsm4(bbk, kb + bj * 16 * 68 * 4);
            unsigned bbv[4];
            ldsm4(bbv, bpv + bj * 32);
            // task A (mt = 2*wm)
            {
                float s0[4] = {}, s1[4] = {};
                mma16(s0, aq0, &bbk[0]);
                mma16(s1, aq0, &bbk[2]);
                float e00 = ex2(s0[0] * Cst), e01 = ex2(s0[1] * Cst);
                float e02 = ex2(s0[2] * Cst), e03 = ex2(s0[3] * Cst);
                float e10 = ex2(s1[0] * Cst), e11 = ex2(s1[1] * Cst);
                float e12 = ex2(s1[2] * Cst), e13 = ex2(s1[3] * Cst);
                sA0 += (e00 + e01) + (e10 + e11);
                sA1 += (e02 + e03) + (e12 + e13);
                unsigned ap4[4] = {packbf(e00, e01), packbf(e02, e03),
                                   packbf(e10, e11), packbf(e12, e13)};
                mma16(oA[0], ap4, &bbv[0]);
                mma16(oA[1], ap4, &bbv[2]);
            }
            // task B (mt = 2*wm+1), shares bbk/bbv
            if (two) {
                float s0[4] = {}, s1[4] = {};
                mma16(s0, aq1, &bbk[0]);
                mma16(s1, aq1, &bbk[2]);
                float e00 = ex2(s0[0] * Cst), e01 = ex2(s0[1] * Cst);
                float e02 = ex2(s0[2] * Cst), e03 = ex2(s0[3] * Cst);
                float e10 = ex2(s1[0] * Cst), e11 = ex2(s1[1] * Cst);
                float e12 = ex2(s1[2] * Cst), e13 = ex2(s1[3] * Cst);
                sB0 += (e00 + e01) + (e10 + e11);
                sB1 += (e02 + e03) + (e12 + e13);
                unsigned ap4[4] = {packbf(e00, e01), packbf(e02, e03),
                                   packbf(e10, e11), packbf(e12, e13)};
                mma16(oB[0], ap4, &bbv[0]);
                mma16(oB[1], ap4, &bbv[2]);
            }
        }
        sA0 += __shfl_xor_sync(0xFFFFFFFFu, sA0, 1);
        sA0 += __shfl_xor_sync(0xFFFFFFFFu, sA0, 2);
        sA1 += __shfl_xor_sync(0xFFFFFFFFu, sA1, 1);
        sA1 += __shfl_xor_sync(0xFFFFFFFFu, sA1, 2);
        float iA0 = 1.f / sA0, iA1 = 1.f / sA1;
        oA[0][0] *= iA0; oA[0][1] *= iA0; oA[0][2] *= iA1; oA[0][3] *= iA1;
        oA[1][0] *= iA0; oA[1][1] *= iA0; oA[1][2] *= iA1; oA[1][3] *= iA1;
        unsigned adA = su(Asu)
            + 4 * ((wm * 32 + (lane & 15)) * 68 + h * 8 + (lane >> 4) * 4);
        stsm4(adA, packbf(oA[0][0], oA[0][1]), packbf(oA[0][2], oA[0][3]),
                   packbf(oA[1][0], oA[1][1]), packbf(oA[1][2], oA[1][3]));

        if (two) {
            sB0 += __shfl_xor_sync(0xFFFFFFFFu, sB0, 1);
            sB0 += __shfl_xor_sync(0xFFFFFFFFu, sB0, 2);
            sB1 += __shfl_xor_sync(0xFFFFFFFFu, sB1, 1);
            sB1 += __shfl_xor_sync(0xFFFFFFFFu, sB1, 2);
            float iB0 = 1.f / sB0, iB1 = 1.f / sB1;
            oB[0][0] *= iB0; oB[0][1] *= iB0; oB[0][2] *= iB1; oB[0][3] *= iB1;
            oB[1][0] *= iB0; oB[1][1] *= iB0; oB[1][2] *= iB1; oB[1][3] *= iB1;
            unsigned adB = su(Asu)
                + 4 * (((wm * 2 + 1) * 16 + (lane & 15)) * 68 + h * 8 + (lane >> 4) * 4);
            stsm4(adB, packbf(oB[0][0], oB[0][1]), packbf(oB[0][2], oB[0][3]),
                       packbf(oB[1][0], oB[1][1]), packbf(oB[1][2], oB[1][3]));
        }
    }
    __syncthreads();   // attn-out in Asu visible
    CP_WAIT0();        // wo resident in B1

    // ================= Output projection =================
    {
        unsigned bbase2[2];
        bbase2[0] = su(B1 + (wn * 32 + brow) * 68 + bcolw);
        bbase2[1] = su(B1 + (wn * 32 + 16 + brow) * 68 + bcolw);

        float c[2][4][4] = {};
#pragma unroll
        for (int kw = 0; kw < 64; kw += 8) {
            unsigned a[2][4], bb[2][4];
            ldsm4(a[0], abase[0] + kw * 4);
            if (wm < 3) ldsm4(a[1], abase[1] + kw * 4);
            ldsm4(bb[0], bbase2[0] + kw * 4);
            ldsm4(bb[1], bbase2[1] + kw * 4);
#pragma unroll
            for (int ni = 0; ni < 4; ni++) {
                mma16(c[0][ni], a[0], &bb[ni >> 1][(ni & 1) * 2]);
                if (wm < 3) mma16(c[1][ni], a[1], &bb[ni >> 1][(ni & 1) * 2]);
            }
        }

        // bias + residual into Ssrc in place
#pragma unroll
        for (int mi = 0; mi < 2; mi++) {
            if (wm == 3 && mi == 1) continue;
#pragma unroll
            for (int ni = 0; ni < 4; ni++) {
#pragma unroll
                for (int r2 = 0; r2 < 2; r2++) {
                    int row = wm * 32 + mi * 16 + gr + r2 * 8;
                    int col = wn * 32 + ni * 8 + 2 * gc;
                    float2 s2 = *(const float2*)&Ssrc[row * 132 + col];
                    float2 y;
                    y.x = c[mi][ni][2 * r2]     + bo[col]     + s2.x;
                    y.y = c[mi][ni][2 * r2 + 1] + bo[col + 1] + s2.y;
                    *(float2*)&Ssrc[row * 132 + col] = y;
                }
            }
        }
    }
    __syncthreads();

    // ================= LayerNorm: 16 warps x 7 rows =================
#pragma unroll
    for (int rr = 0; rr < 7; rr++) {
        int r = warp * 7 + rr;
        float4 v4 = *(const float4*)&Ssrc[r * 132 + lane * 4];
        float vals[4] = {v4.x, v4.y, v4.z, v4.w};
        float s1 = vals[0] + vals[1] + vals[2] + vals[3];
        float s2 = vals[0]*vals[0] + vals[1]*vals[1] + vals[2]*vals[2] + vals[3]*vals[3];
#pragma unroll
        for (int off = 16; off > 0; off >>= 1) {
            s1 += __shfl_xor_sync(0xFFFFFFFFu, s1, off);
            s2 += __shfl_xor_sync(0xFFFFFFFFu, s2, off);
        }
        float mu = s1 * (1.f / 128.f);
        float var = s2 * (1.f / 128.f) - mu * mu;
        float inv = rsqrtf(var + 1e-5f);
#pragma unroll
        for (int j = 0; j < 4; j++) {
            int cidx = lane * 4 + j;
            out[((size_t)b * CC + r) * DD + cidx] =
                (vals[j] - mu) * inv * lg[cidx] + lb[cidx];
        }
    }
}

// ---------------------------------------------------------------------------
extern "C" void kernel_launch(void* const* d_in, const int* in_sizes, int n_in,
                              void* d_out, int out_size) {
    const float* x   = (const float*)d_in[0];
    const float* cw  = (const float*)d_in[1];
    const float* cb  = (const float*)d_in[2];
    const float* bg  = (const float*)d_in[3];
    const float* bb_ = (const float*)d_in[4];
    const float* bm  = (const float*)d_in[5];
    const float* bvv = (const float*)d_in[6];
    const float* wq  = (const float*)d_in[7];
    const float* bq  = (const float*)d_in[8];
    const float* wk  = (const float*)d_in[9];
    const float* bk  = (const float*)d_in[10];
    const float* wv  = (const float*)d_in[11];
    const float* bv  = (const float*)d_in[12];
    const float* wo  = (const float*)d_in[13];
    const float* bo  = (const float*)d_in[14];
    const float* lg  = (const float*)d_in[15];
    const float* lb  = (const float*)d_in[16];
    float* out = (float*)d_out;

    const int FUSED_SMEM = SMEM_W * 4;   // 220416 B
    cudaFuncSetAttribute(k_fused, cudaFuncAttributeMaxDynamicSharedMemorySize, FUSED_SMEM);

    k_prep<<<64, 256>>>(wq, wk, wv, wo);
    k_fused<<<BB, NT, FUSED_SMEM>>>(x, cw, cb, bg, bb_, bm, bvv,
                                    bq, bk, bv, bo, lg, lb, out);
}

// round 16
// speedup vs baseline: 1.1742x; 1.1742x over previous
#include <cuda_runtime.h>
#include <cuda_bf16.h>
#include <cstdint>

#define BB 512
#define CC 112
#define DD 128
#define HH 8
#define HDIM 16
#define KW 8
#define MM (BB*CC)   // 57344
#define NT 512

// smem word offsets
#define ASU_O   14784    // bf16 A [112][68]; attn-out overlay
#define B0_O    22400    // weight buf [128][68]; LN partials overlay
#define B1_O    31104    // weight buf [128][68]
#define KALL_O  39808    // K [112][68]
#define VT_O    47424    // V^T [128][60]
#define SMEM_W  55104    // 220416 bytes

// Scratch (allocation-free contract)
__device__ __nv_bfloat16 g_wb[4 * DD * DD];        // bf16 wq|wk|wv|wo

__device__ __forceinline__ unsigned packbf(float a, float b) {
    __nv_bfloat162 p = __floats2bfloat162_rn(a, b);
    return *reinterpret_cast<unsigned*>(&p);
}
__device__ __forceinline__ float ex2(float x) {
    float r;
    asm("ex2.approx.f32 %0, %1;" : "=f"(r) : "f"(x));
    return r;
}
__device__ __forceinline__ void mma16(float* c, const unsigned* a, const unsigned* b) {
    asm volatile(
        "mma.sync.aligned.m16n8k16.row.col.f32.bf16.bf16.f32 "
        "{%0,%1,%2,%3}, {%4,%5,%6,%7}, {%8,%9}, {%0,%1,%2,%3};"
        : "+f"(c[0]), "+f"(c[1]), "+f"(c[2]), "+f"(c[3])
        : "r"(a[0]), "r"(a[1]), "r"(a[2]), "r"(a[3]), "r"(b[0]), "r"(b[1]));
}
__device__ __forceinline__ void ldsm4(unsigned* r, unsigned addr) {
    asm volatile("ldmatrix.sync.aligned.m8n8.x4.shared.b16 {%0,%1,%2,%3}, [%4];"
        : "=r"(r[0]), "=r"(r[1]), "=r"(r[2]), "=r"(r[3]) : "r"(addr));
}
__device__ __forceinline__ void stsm2(unsigned addr, unsigned r0, unsigned r1) {
    asm volatile("stmatrix.sync.aligned.m8n8.x2.shared.b16 [%0], {%1,%2};"
        :: "r"(addr), "r"(r0), "r"(r1) : "memory");
}
__device__ __forceinline__ void stsm2t(unsigned addr, unsigned r0, unsigned r1) {
    asm volatile("stmatrix.sync.aligned.m8n8.x2.trans.shared.b16 [%0], {%1,%2};"
        :: "r"(addr), "r"(r0), "r"(r1) : "memory");
}
__device__ __forceinline__ void stsm4(unsigned addr, unsigned r0, unsigned r1,
                                      unsigned r2, unsigned r3) {
    asm volatile("stmatrix.sync.aligned.m8n8.x4.shared.b16 [%0], {%1,%2,%3,%4};"
        :: "r"(addr), "r"(r0), "r"(r1), "r"(r2), "r"(r3) : "memory");
}
__device__ __forceinline__ unsigned su(const void* p) {
    return (unsigned)__cvta_generic_to_shared(p);
}
__device__ __forceinline__ void cpa16(unsigned dst, const void* src) {
    asm volatile("cp.async.cg.shared.global [%0], [%1], 16;" :: "r"(dst), "l"(src));
}
#define CP_COMMIT() asm volatile("cp.async.commit_group;")
#define CP_WAIT0()  asm volatile("cp.async.wait_group 0;")
#define CP_WAIT1()  asm volatile("cp.async.wait_group 1;")

// ---------------------------------------------------------------------------
// Kernel 0: weights fp32 -> bf16 (wq|wk|wv|wo)
// ---------------------------------------------------------------------------
__global__ void k_prep(const float* __restrict__ wq, const float* __restrict__ wk,
                       const float* __restrict__ wv, const float* __restrict__ wo) {
    int m = blockIdx.x >> 4;
    const float* s = (m == 0) ? wq : (m == 1) ? wk : (m == 2) ? wv : wo;
    int i = ((blockIdx.x & 15) * 256 + threadIdx.x) * 4;
    float4 v = *(const float4*)(s + i);
    uint2 p = {packbf(v.x, v.y), packbf(v.z, v.w)};
    *(uint2*)(g_wb + m * DD * DD + i) = p;
}

// ---------------------------------------------------------------------------
// Kernel 1 (FULLY FUSED): conv -> QKV -> attention(single-pass) ->
//                         outproj with fused bias/residual/LayerNorm epilogue.
// ---------------------------------------------------------------------------
__global__ void __launch_bounds__(NT) k_fused(
        const float* __restrict__ x,
        const float* __restrict__ cw, const float* __restrict__ cb,
        const float* __restrict__ bg, const float* __restrict__ bbias,
        const float* __restrict__ bm, const float* __restrict__ bvv,
        const float* __restrict__ bq, const float* __restrict__ bk,
        const float* __restrict__ bvp, const float* __restrict__ bo,
        const float* __restrict__ lg, const float* __restrict__ lb,
        float* __restrict__ out) {
    extern __shared__ unsigned smu[];
    float*    Ssrc = (float*)smu;          // [112][132] fp32
    unsigned* Asu  = smu + ASU_O;
    unsigned* B0   = smu + B0_O;
    unsigned* B1   = smu + B1_O;
    unsigned* kall = smu + KALL_O;
    unsigned* vt   = smu + VT_O;

    int tid = threadIdx.x;
    int b = blockIdx.x;
    int lane = tid & 31, warp = tid >> 5;   // 16 warps
    int wm = warp >> 2, wn = warp & 3;      // 4 x 4, warp tile 32x32
    int gr = lane >> 2, gc = lane & 3;

    int arow = (lane & 7) + ((lane >> 3) & 1) * 8;
    int acolw = (lane >> 4) * 4;
    int brow = (lane & 7) + ((lane >> 4) & 1) * 8;
    int bcolw = ((lane >> 3) & 1) * 4;

    // ================= stage x (group0) then wq (group1) =================
    const char* xg = (const char*)(x + (size_t)b * CC * DD);
#pragma unroll
    for (int i = tid; i < 3584; i += NT) {
        int row = i >> 5, c4 = (i & 31) * 4;
        cpa16(su(Ssrc + row * 132 + c4), xg + (row * 128 + c4) * 4);
    }
    CP_COMMIT();
#pragma unroll
    for (int i = tid; i < 2048; i += NT) {
        int row = i >> 4, q4 = i & 15;
        cpa16(su(B0 + row * 68 + q4 * 4), (const char*)g_wb + i * 16);
    }
    CP_COMMIT();
    CP_WAIT1();        // x resident (wq may still be in flight)
    __syncthreads();

    // ================= conv -> GELU -> BN -> residual (in smem) ============
    {
#pragma unroll
        for (int rr = 0; rr < 7; rr++) {
            int row = warp * 7 + rr;
            int c0 = lane * 4;
            float xin[11];
#pragma unroll
            for (int j = 0; j < 11; j++) {
                int idx = c0 - 3 + j;
                xin[j] = (idx >= 0 && idx < DD) ? Ssrc[row * 132 + idx] : 0.f;
            }
            float w[KW];
#pragma unroll
            for (int k = 0; k < KW; k++) w[k] = cw[row * KW + k];
            float cbias = cb[row];
            float bnsc = bg[row] * rsqrtf(bvv[row] + 1e-5f);
            float bnm = bm[row], bnb = bbias[row];
            __syncwarp();
            float so[4];
#pragma unroll
            for (int j = 0; j < 4; j++) {
                float acc = 0.f;
#pragma unroll
                for (int k = 0; k < KW; k++) acc += xin[j + k] * w[k];
                acc += cbias;
                float g = 0.5f * acc * (1.f + erff(acc * 0.70710678118654752f));
                float h = (g - bnm) * bnsc + bnb;
                so[j] = xin[j + 3] + h;
            }
            *(float4*)&Ssrc[row * 132 + c0] = make_float4(so[0], so[1], so[2], so[3]);
            Asu[row * 68 + (c0 >> 1)]     = packbf(so[0], so[1]);
            Asu[row * 68 + (c0 >> 1) + 1] = packbf(so[2], so[3]);
        }
    }
    CP_WAIT0();        // wq resident
    __syncthreads();

    unsigned abase[2];
    abase[0] = su(Asu + (wm * 32 + arow) * 68 + acolw);
    abase[1] = su(Asu + (wm * 32 + 16 + arow) * 68 + acolw);

    unsigned qf[4][4];   // register-resident Q fragments (2 used when wm==3)

    // ================= QKV GEMMs (double-buffered weights) =================
    for (int sel = 0; sel < 3; sel++) {
        {   // prefetch next weight matrix (wk, wv, then wo)
            const char* nw = (const char*)g_wb + (size_t)((sel < 2) ? sel + 1 : 3) * 32768;
            unsigned* dstb = (sel == 1) ? B0 : B1;
#pragma unroll
            for (int i = tid; i < 2048; i += NT) {
                int row = i >> 4, q4 = i & 15;
                cpa16(su(dstb + row * 68 + q4 * 4), nw + i * 16);
            }
            CP_COMMIT();
        }
        unsigned* Bsu = (sel & 1) ? B1 : B0;
        unsigned bbase[2];
        bbase[0] = su(Bsu + (wn * 32 + brow) * 68 + bcolw);
        bbase[1] = su(Bsu + (wn * 32 + 16 + brow) * 68 + bcolw);

        float c[2][4][4] = {};
#pragma unroll
        for (int kw = 0; kw < 64; kw += 8) {
            unsigned a[2][4], bb[2][4];
            ldsm4(a[0], abase[0] + kw * 4);
            if (wm < 3) ldsm4(a[1], abase[1] + kw * 4);
            ldsm4(bb[0], bbase[0] + kw * 4);
            ldsm4(bb[1], bbase[1] + kw * 4);
#pragma unroll
            for (int ni = 0; ni < 4; ni++) {
                mma16(c[0][ni], a[0], &bb[ni >> 1][(ni & 1) * 2]);
                if (wm < 3) mma16(c[1][ni], a[1], &bb[ni >> 1][(ni & 1) * 2]);
            }
        }

        const float* bias = (sel == 0) ? bq : (sel == 1) ? bk : bvp;
#pragma unroll
        for (int mi = 0; mi < 2; mi++) {
            if (wm == 3 && mi == 1) continue;   // rows 112..127 are padding
            int R0 = wm * 32 + mi * 16;
#pragma unroll
            for (int ni = 0; ni < 4; ni++) {
                int C0 = wn * 32 + ni * 8;
                int col = C0 + 2 * gc;
                float v0 = c[mi][ni][0] + bias[col];
                float v1 = c[mi][ni][1] + bias[col + 1];
                float v2 = c[mi][ni][2] + bias[col];
                float v3 = c[mi][ni][3] + bias[col + 1];
                if (sel == 0) {
                    int hp = ni >> 1, p = ni & 1;
                    int idx = mi * 2 + hp;
                    qf[idx][p * 2]     = packbf(v0, v1);
                    qf[idx][p * 2 + 1] = packbf(v2, v3);
                } else if (sel == 1) {
                    unsigned ad = su(kall) + 4 * ((R0 + (lane & 15)) * 68 + (C0 >> 1));
                    stsm2(ad, packbf(v0, v1), packbf(v2, v3));
                } else {
                    unsigned ad = su(vt) + (C0 + (lane & 7)) * 240 + (R0 + (lane & 8)) * 2;
                    stsm2t(ad, packbf(v0, v1), packbf(v2, v3));
                }
            }
        }
        if (sel < 2) { CP_WAIT0(); __syncthreads(); }
        else         { __syncthreads(); }   // kall/vt visible; wo still in flight
    }

    // ================= Attention: single-pass QK->softmax->PV ==============
    const float Cst = 0.25f * 1.44269504088896f;
#pragma unroll
    for (int hp = 0; hp < 2; hp++) {
        int nmi = (wm < 3) ? 2 : 1;
        for (int mi = 0; mi < nmi; mi++) {
            int mt = wm * 2 + mi;
            int h = wn * 2 + hp;
            const unsigned* aq = qf[mi * 2 + hp];

            float sum0 = 0.f, sum1 = 0.f;
            float o[2][4] = {};
            unsigned bpv = su(vt + (h * 16 + brow) * 60 + bcolw);
#pragma unroll
            for (int bj = 0; bj < 7; bj++) {
                unsigned bbk[4];
                ldsm4(bbk, su(kall + (bj * 16 + brow) * 68 + h * 8 + bcolw));
                float s0[4] = {}, s1[4] = {};
                mma16(s0, aq, &bbk[0]);
                mma16(s1, aq, &bbk[2]);
                float e00 = ex2(s0[0] * Cst), e01 = ex2(s0[1] * Cst);
                float e02 = ex2(s0[2] * Cst), e03 = ex2(s0[3] * Cst);
                float e10 = ex2(s1[0] * Cst), e11 = ex2(s1[1] * Cst);
                float e12 = ex2(s1[2] * Cst), e13 = ex2(s1[3] * Cst);
                sum0 += (e00 + e01) + (e10 + e11);
                sum1 += (e02 + e03) + (e12 + e13);
                unsigned ap4[4];
                ap4[0] = packbf(e00, e01);
                ap4[1] = packbf(e02, e03);
                ap4[2] = packbf(e10, e11);
                ap4[3] = packbf(e12, e13);
                unsigned bbv[4];
                ldsm4(bbv, bpv + bj * 32);
                mma16(o[0], ap4, &bbv[0]);
                mma16(o[1], ap4, &bbv[2]);
            }
            sum0 += __shfl_xor_sync(0xFFFFFFFFu, sum0, 1);
            sum0 += __shfl_xor_sync(0xFFFFFFFFu, sum0, 2);
            sum1 += __shfl_xor_sync(0xFFFFFFFFu, sum1, 1);
            sum1 += __shfl_xor_sync(0xFFFFFFFFu, sum1, 2);
            float inv0 = 1.f / sum0, inv1 = 1.f / sum1;

            o[0][0] *= inv0; o[0][1] *= inv0; o[0][2] *= inv1; o[0][3] *= inv1;
            o[1][0] *= inv0; o[1][1] *= inv0; o[1][2] *= inv1; o[1][3] *= inv1;
            unsigned ad = su(Asu)
                + 4 * ((mt * 16 + (lane & 15)) * 68 + h * 8 + (lane >> 4) * 4);
            stsm4(ad, packbf(o[0][0], o[0][1]), packbf(o[0][2], o[0][3]),
                      packbf(o[1][0], o[1][1]), packbf(o[1][2], o[1][3]));
        }
    }
    __syncthreads();   // attn-out in Asu visible
    CP_WAIT0();        // wo resident in B1

    // ================= Output projection + fused bias/residual/LN ==========
    {
        unsigned bbase2[2];
        bbase2[0] = su(B1 + (wn * 32 + brow) * 68 + bcolw);
        bbase2[1] = su(B1 + (wn * 32 + 16 + brow) * 68 + bcolw);

        float c[2][4][4] = {};
#pragma unroll
        for (int kw = 0; kw < 64; kw += 8) {
            unsigned a[2][4], bb[2][4];
            ldsm4(a[0], abase[0] + kw * 4);
            if (wm < 3) ldsm4(a[1], abase[1] + kw * 4);
            ldsm4(bb[0], bbase2[0] + kw * 4);
            ldsm4(bb[1], bbase2[1] + kw * 4);
#pragma unroll
            for (int ni = 0; ni < 4; ni++) {
                mma16(c[0][ni], a[0], &bb[ni >> 1][(ni & 1) * 2]);
                if (wm < 3) mma16(c[1][ni], a[1], &bb[ni >> 1][(ni & 1) * 2]);
            }
        }

        // y = c + bo + src (in registers); per-(row, wn-strip) LN partials
        float* part = (float*)B0;   // [112][8]: (s1,s2) x 4 wn strips
#pragma unroll
        for (int mi = 0; mi < 2; mi++) {
            if (wm == 3 && mi == 1) continue;
#pragma unroll
            for (int r2 = 0; r2 < 2; r2++) {
                int row = wm * 32 + mi * 16 + gr + r2 * 8;
                float s1 = 0.f, s2 = 0.f;
#pragma unroll
                for (int ni = 0; ni < 4; ni++) {
                    int col = wn * 32 + ni * 8 + 2 * gc;
                    float2 sv = *(const float2*)&Ssrc[row * 132 + col];
                    float y0 = c[mi][ni][2 * r2]     + bo[col]     + sv.x;
                    float y1 = c[mi][ni][2 * r2 + 1] + bo[col + 1] + sv.y;
                    c[mi][ni][2 * r2]     = y0;
                    c[mi][ni][2 * r2 + 1] = y1;
                    s1 += y0 + y1;
                    s2 += y0 * y0 + y1 * y1;
                }
                s1 += __shfl_xor_sync(0xFFFFFFFFu, s1, 1);
                s1 += __shfl_xor_sync(0xFFFFFFFFu, s1, 2);
                s2 += __shfl_xor_sync(0xFFFFFFFFu, s2, 1);
                s2 += __shfl_xor_sync(0xFFFFFFFFu, s2, 2);
                if (gc == 0) {
                    part[row * 8 + wn * 2]     = s1;
                    part[row * 8 + wn * 2 + 1] = s2;
                }
            }
        }
        __syncthreads();

        // normalize + store directly from registers
#pragma unroll
        for (int mi = 0; mi < 2; mi++) {
            if (wm == 3 && mi == 1) continue;
#pragma unroll
            for (int r2 = 0; r2 < 2; r2++) {
                int row = wm * 32 + mi * 16 + gr + r2 * 8;
                const float* pr = part + row * 8;
                float t1 = (pr[0] + pr[2]) + (pr[4] + pr[6]);
                float t2 = (pr[1] + pr[3]) + (pr[5] + pr[7]);
                float mu = t1 * (1.f / 128.f);
                float var = t2 * (1.f / 128.f) - mu * mu;
                float inv = rsqrtf(var + 1e-5f);
                float* op = out + ((size_t)b * CC + row) * DD;
#pragma unroll
                for (int ni = 0; ni < 4; ni++) {
                    int col = wn * 32 + ni * 8 + 2 * gc;
                    float2 o2;
                    o2.x = (c[mi][ni][2 * r2]     - mu) * inv * lg[col]     + lb[col];
                    o2.y = (c[mi][ni][2 * r2 + 1] - mu) * inv * lg[col + 1] + lb[col + 1];
                    *(float2*)(op + col) = o2;
                }
            }
        }
    }
}

// ---------------------------------------------------------------------------
extern "C" void kernel_launch(void* const* d_in, const int* in_sizes, int n_in,
                              void* d_out, int out_size) {
    const float* x   = (const float*)d_in[0];
    const float* cw  = (const float*)d_in[1];
    const float* cb  = (const float*)d_in[2];
    const float* bg  = (const float*)d_in[3];
    const float* bb_ = (const float*)d_in[4];
    const float* bm  = (const float*)d_in[5];
    const float* bvv = (const float*)d_in[6];
    const float* wq  = (const float*)d_in[7];
    const float* bq  = (const float*)d_in[8];
    const float* wk  = (const float*)d_in[9];
    const float* bk  = (const float*)d_in[10];
    const float* wv  = (const float*)d_in[11];
    const float* bv  = (const float*)d_in[12];
    const float* wo  = (const float*)d_in[13];
    const float* bo  = (const float*)d_in[14];
    const float* lg  = (const float*)d_in[15];
    const float* lb  = (const float*)d_in[16];
    float* out = (float*)d_out;

    const int FUSED_SMEM = SMEM_W * 4;   // 220416 B
    cudaFuncSetAttribute(k_fused, cudaFuncAttributeMaxDynamicSharedMemorySize, FUSED_SMEM);

    k_prep<<<64, 256>>>(wq, wk, wv, wo);
    k_fused<<<BB, NT, FUSED_SMEM>>>(x, cw, cb, bg, bb_, bm, bvv,
                                    bq, bk, bv, bo, lg, lb, out);
}